// round 15
// baseline (speedup 1.0000x reference)
#include <cuda_runtime.h>
#include <cuda_fp16.h>
#include <cuda_bf16.h>
#include <math.h>

#define Bb   512
#define Hh   256
#define Ld   256
#define Tt   64
#define Vv   128
#define NL   2
#define G    4
#define NTH  1024

// ---------------- packed bf16 weights (R13 layout) + transposed bf16 encoder ---------
#define OFF_ATTNH 0         // attn h-part: K=256,N=256 -> 65536
#define OFF_COMBA 65536     // comb applied-part:       -> 65536
#define OFF_GIH   131072    // 2 x 256x768 -> 393216
#define OFF_GHH   524288    // 2 x 256x768 -> 393216
#define OFF_OUT   917504    // 256x128 -> 32768
#define PACK_TOTAL 950272

#define PACK_BLOCKS 3712
#define ENC_BLOCKS  8192    // 512 b x 16 tiles (64h x 64l)
#define TOK_BLOCKS  256

__device__ __align__(16) __nv_bfloat16 g_pack[PACK_TOTAL];
__device__ __align__(16) __nv_bfloat16 g_encT[(size_t)Bb * Ld * Hh];  // [B][L][H]
__device__ __align__(16) float  g_Tattn[Vv * Ld];
__device__ __align__(16) float  g_Tcomb[Vv * Hh];

__global__ void pack_all_kernel(const float* __restrict__ aw, const float* __restrict__ cw,
                                const float* __restrict__ gih, const float* __restrict__ ghh,
                                const float* __restrict__ ow, const float* __restrict__ x,
                                const float* __restrict__ emb, const float* __restrict__ ab,
                                const float* __restrict__ cb)
{
    if (blockIdx.x < PACK_BLOCKS) {
        int i = blockIdx.x * blockDim.x + threadIdx.x;
        if (i >= PACK_TOTAL) return;
        float v;
        if (i < 65536) {                        // attn h-part: W[j][256 + k]
            int c = i & 3, j = (i >> 2) & 255, k4 = i >> 10;
            v = aw[j * 512 + 256 + k4 * 4 + c];
        } else if (i < 131072) {                // comb applied-part: W[j][k]
            int r = i - 65536;
            int c = r & 3, j = (r >> 2) & 255, k4 = r >> 10;
            v = cw[j * 512 + k4 * 4 + c];
        } else if (i < 524288) {                // gru ih
            int r = i - 131072;
            int layer = r / 196608; int q = r % 196608;
            int c = q & 3; int t2 = q >> 2; int j = t2 % 768; int k4 = t2 / 768;
            v = gih[layer * 196608 + j * 256 + k4 * 4 + c];
        } else if (i < 917504) {                // gru hh
            int r = i - 524288;
            int layer = r / 196608; int q = r % 196608;
            int c = q & 3; int t2 = q >> 2; int j = t2 % 768; int k4 = t2 / 768;
            v = ghh[layer * 196608 + j * 256 + k4 * 4 + c];
        } else {                                // out
            int r = i - 917504;
            int c = r & 3, j = (r >> 2) & 127, k4 = r >> 9;
            v = ow[j * 256 + k4 * 4 + c];
        }
        g_pack[i] = __float2bfloat16(v);
    } else if (blockIdx.x < PACK_BLOCKS + ENC_BLOCKS) {
        // encoder transpose: x[B][H][1][L] -> g_encT[B][L][H], 64x64 tiles
        __shared__ float tile[64][65];
        int bid = blockIdx.x - PACK_BLOCKS;
        int b  = bid >> 4;
        int tl = bid & 15;
        int h0 = (tl >> 2) * 64;
        int l0 = (tl & 3) * 64;
        int t = threadIdx.x;
        #pragma unroll
        for (int i = 0; i < 16; i++) {
            int idx = i * 256 + t;
            int r = idx >> 6, c = idx & 63;
            tile[r][c] = x[((size_t)b * Hh + h0 + r) * Ld + l0 + c];
        }
        __syncthreads();
        #pragma unroll
        for (int i = 0; i < 16; i++) {
            int idx = i * 256 + t;
            int r = idx >> 6, c = idx & 63;
            g_encT[((size_t)b * Ld + l0 + r) * Hh + h0 + c] = __float2bfloat16(tile[c][r]);
        }
    } else {
        __shared__ float se[Hh];
        int bid = blockIdx.x - PACK_BLOCKS - ENC_BLOCKS;
        int tok = bid & 127;
        bool isComb = bid >= 128;
        int j = threadIdx.x;
        se[j] = emb[tok * Hh + j];
        __syncthreads();
        const float* W = isComb ? (cw + j * 512 + 256) : (aw + j * 512);
        float s = 0.f;
        #pragma unroll 8
        for (int k = 0; k < 256; k++) s += W[k] * se[k];
        if (isComb) g_Tcomb[tok * Hh + j] = s + cb[j];
        else        g_Tattn[tok * Ld + j] = s + ab[j];
    }
}

// ---------------- f32x2 / bf16 helpers ----------------
typedef unsigned long long u64;

__device__ __forceinline__ void fma2(u64& d, u64 a, u64 b) {
    asm("fma.rn.f32x2 %0, %1, %2, %0;" : "+l"(d) : "l"(a), "l"(b));
}
__device__ __forceinline__ float sum2(u64 v) {
    return __uint_as_float((unsigned)v) + __uint_as_float((unsigned)(v >> 32));
}
__device__ __forceinline__ u64 cvt2(unsigned u) {   // bf16x2 -> f32x2, ALU only
    return ((u64)(u & 0xFFFF0000u) << 32) | (u64)(u << 16);
}
__device__ __forceinline__ u64 dup2(float a) {
    unsigned ua = __float_as_uint(a);
    return ((u64)ua << 32) | (u64)ua;
}

// ---------------- block reduce (4 values, 32 warps) ----------------
__device__ __forceinline__ void block_reduce4(float v[G], float* sm, int tid, bool is_max) {
    __syncthreads();
    #pragma unroll
    for (int g = 0; g < G; g++) {
        #pragma unroll
        for (int o = 16; o > 0; o >>= 1) {
            float oth = __shfl_xor_sync(0xffffffffu, v[g], o);
            v[g] = is_max ? fmaxf(v[g], oth) : (v[g] + oth);
        }
    }
    int wid = tid >> 5;
    if ((tid & 31) == 0) {
        #pragma unroll
        for (int g = 0; g < G; g++) sm[wid * G + g] = v[g];
    }
    __syncthreads();
    #pragma unroll
    for (int g = 0; g < G; g++) {
        float r = sm[g];
        #pragma unroll
        for (int w = 1; w < 32; w++)
            r = is_max ? fmaxf(r, sm[w * G + g]) : (r + sm[w * G + g]);
        v[g] = r;
    }
}

// ---------------- main persistent decoder kernel ----------------
// 128 CTAs x 1024 threads. Two independent 512-thread groups per CTA:
// group grp = tid>>9 owns batch rows {2*grp, 2*grp+1}. Within a group:
// lo/hi halves split every matvec's K dimension (R12 structure, G=2).
__global__ __launch_bounds__(NTH)
void decoder_kernel(const int*   __restrict__ y,
                    const float* __restrict__ gbi,
                    const float* __restrict__ gbh,
                    const float* __restrict__ out_b,
                    float* __restrict__ outp,
                    float* __restrict__ attnp)
{
    __shared__ __align__(16) float s_h  [NL][G][Hh];
    __shared__ __align__(16) float s_aw [G][Ld];
    __shared__ __align__(16) float s_app[G][Hh];
    __shared__ __align__(16) float s_x  [G][Hh];
    __shared__ __align__(16) float s_p2 [G][3][Hh];
    __shared__ __align__(16) float s_out[G][Vv][8];
    __shared__ float s_red[32 * G];
    __shared__ int   s_tok[G];

    const int tid  = threadIdx.x;
    const int grp  = tid >> 9;           // 0/1: owns rows {2grp, 2grp+1}
    const int tid2 = tid & 511;
    const int jj   = tid2 & 255;
    const bool hi  = (tid2 >= 256);
    const int r0   = grp * 2;
    const int b0   = blockIdx.x * G;

    const __nv_bfloat16* Pattnh = g_pack + OFF_ATTNH;
    const __nv_bfloat16* Pcomba = g_pack + OFF_COMBA;
    const __nv_bfloat16* Pgih   = g_pack + OFF_GIH;
    const __nv_bfloat16* Pghh   = g_pack + OFF_GHH;
    const __nv_bfloat16* Pout   = g_pack + OFF_OUT;

    for (int i = tid; i < NL * G * Hh; i += NTH)
        (&s_h[0][0][0])[i] = 0.f;
    __syncthreads();

    for (int t = 0; t < Tt; t++) {
        // -------- token fetch --------
        if (tid < G)
            s_tok[tid] = (t == 0) ? 0 : y[(b0 + tid) * Tt + t - 1];
        __syncthreads();

        // -------- attention scores: per group, h-part lo/hi K-halves --------
        {
            u64 acc[2] = {0, 0};
            const uint2* W = (const uint2*)Pattnh + (hi ? 32 * 256 : 0) + jj;
            const int kbase = hi ? 32 : 0;
            #pragma unroll 8
            for (int k4 = 0; k4 < 32; k4++) {
                uint2 wh = W[k4 * 256];
                u64 wx = cvt2(wh.x), wy = cvt2(wh.y);
                #pragma unroll
                for (int g = 0; g < 2; g++) {
                    ulonglong2 xv = ((const ulonglong2*)(&s_h[0][r0 + g][0]))[kbase + k4];
                    fma2(acc[g], wx, xv.x);
                    fma2(acc[g], wy, xv.y);
                }
            }
            if (hi) {
                #pragma unroll
                for (int g = 0; g < 2; g++) s_p2[r0 + g][0][jj] = sum2(acc[g]);
            }
            __syncthreads();

            // softmax (ownership-masked over all 4 rows, 32 warps)
            float sc[G];
            #pragma unroll
            for (int r = 0; r < G; r++) {
                bool own = (!hi) && ((r >> 1) == grp);
                sc[r] = own ? (sum2(acc[r & 1]) + s_p2[r][0][jj]
                               + g_Tattn[s_tok[r] * Ld + jj])
                            : -1e30f;
            }
            float m[G];
            #pragma unroll
            for (int r = 0; r < G; r++) m[r] = sc[r];
            block_reduce4(m, s_red, tid, true);
            float p[G];
            #pragma unroll
            for (int r = 0; r < G; r++)
                p[r] = ((!hi) && ((r >> 1) == grp)) ? __expf(sc[r] - m[r]) : 0.f;
            float s[G];
            #pragma unroll
            for (int r = 0; r < G; r++) s[r] = p[r];
            block_reduce4(s, s_red, tid, false);
            if (!hi) {
                #pragma unroll
                for (int g = 0; g < 2; g++) {
                    int r = r0 + g;
                    float a = p[r] * (1.f / s[r]);
                    s_aw[r][jj] = a;
                    attnp[((size_t)(b0 + r) * Tt + t) * Ld + jj] = a;
                }
            }
            __syncthreads();
        }

        // -------- applied = aw @ encT (thread owns (row, l-half, h-pair)) --------
        {
            const int row = tid >> 8;            // 0..3
            const int rem = tid & 255;
            const int lh  = rem >> 7;            // l-half 0/1
            const int h2  = rem & 127;           // h pair
            const unsigned* ep =
                (const unsigned*)(g_encT + (size_t)(b0 + row) * Ld * Hh) + h2;
            const float4* awp = (const float4*)(s_aw[row]);
            u64 acc = 0;
            const int lb0 = lh * 128;
            #pragma unroll
            for (int lb = 0; lb < 128; lb += 8) {
                unsigned e[8];
                #pragma unroll
                for (int u = 0; u < 8; u++) e[u] = ep[(lb0 + lb + u) * 128];
                float4 a0 = awp[(lb0 + lb) >> 2];
                float4 a1 = awp[((lb0 + lb) >> 2) + 1];
                fma2(acc, cvt2(e[0]), dup2(a0.x));
                fma2(acc, cvt2(e[1]), dup2(a0.y));
                fma2(acc, cvt2(e[2]), dup2(a0.z));
                fma2(acc, cvt2(e[3]), dup2(a0.w));
                fma2(acc, cvt2(e[4]), dup2(a1.x));
                fma2(acc, cvt2(e[5]), dup2(a1.y));
                fma2(acc, cvt2(e[6]), dup2(a1.z));
                fma2(acc, cvt2(e[7]), dup2(a1.w));
            }
            ((float2*)&s_p2[0][0][0])[(row * 128 + h2) * 2 + lh] =
                make_float2(__uint_as_float((unsigned)acc),
                            __uint_as_float((unsigned)(acc >> 32)));
        }
        __syncthreads();
        if (tid < 512) {       // combine the two l-half partials
            int row = tid >> 7, h2 = tid & 127;
            float2 pa = ((const float2*)&s_p2[0][0][0])[(row * 128 + h2) * 2];
            float2 pb = ((const float2*)&s_p2[0][0][0])[(row * 128 + h2) * 2 + 1];
            ((float2*)&s_app[row][0])[h2] = make_float2(pa.x + pb.x, pa.y + pb.y);
        }
        __syncthreads();

        // -------- combine: per group, applied-part lo/hi K-halves --------
        {
            u64 acc[2] = {0, 0};
            const uint2* W = (const uint2*)Pcomba + (hi ? 32 * 256 : 0) + jj;
            const int kbase = hi ? 32 : 0;
            #pragma unroll 8
            for (int k4 = 0; k4 < 32; k4++) {
                uint2 wh = W[k4 * 256];
                u64 wx = cvt2(wh.x), wy = cvt2(wh.y);
                #pragma unroll
                for (int g = 0; g < 2; g++) {
                    ulonglong2 xv = ((const ulonglong2*)(&s_app[r0 + g][0]))[kbase + k4];
                    fma2(acc[g], wx, xv.x);
                    fma2(acc[g], wy, xv.y);
                }
            }
            if (hi) {
                #pragma unroll
                for (int g = 0; g < 2; g++) s_p2[r0 + g][0][jj] = sum2(acc[g]);
            }
            __syncthreads();
            if (!hi) {
                #pragma unroll
                for (int g = 0; g < 2; g++) {
                    int r = r0 + g;
                    s_x[r][jj] = fmaxf(sum2(acc[g]) + s_p2[r][0][jj]
                                       + g_Tcomb[s_tok[r] * Hh + jj], 0.f);
                }
            }
            __syncthreads();
        }

        // -------- GRU layers: per group, lo = ih, hi = hh --------
        #pragma unroll
        for (int l = 0; l < NL; l++) {
            u64 a0[2] = {0,0}, a1[2] = {0,0}, a2[2] = {0,0};
            const uint2* W =
                (const uint2*)((hi ? Pghh : Pgih) + l * 196608) + jj;
            const float* vb = hi ? &s_h[l][r0][0] : &s_x[r0][0];
            #pragma unroll 4
            for (int k4 = 0; k4 < 64; k4++) {
                uint2 wh0 = W[k4 * 768];
                uint2 wh1 = W[k4 * 768 + 256];
                uint2 wh2 = W[k4 * 768 + 512];
                u64 w0x = cvt2(wh0.x), w0y = cvt2(wh0.y);
                u64 w1x = cvt2(wh1.x), w1y = cvt2(wh1.y);
                u64 w2x = cvt2(wh2.x), w2y = cvt2(wh2.y);
                #pragma unroll
                for (int g = 0; g < 2; g++) {
                    ulonglong2 xv = ((const ulonglong2*)(vb + g * Hh))[k4];
                    fma2(a0[g], w0x, xv.x); fma2(a0[g], w0y, xv.y);
                    fma2(a1[g], w1x, xv.x); fma2(a1[g], w1y, xv.y);
                    fma2(a2[g], w2x, xv.x); fma2(a2[g], w2y, xv.y);
                }
            }
            if (hi) {
                #pragma unroll
                for (int g = 0; g < 2; g++) {
                    s_p2[r0 + g][0][jj] = sum2(a0[g]);
                    s_p2[r0 + g][1][jj] = sum2(a1[g]);
                    s_p2[r0 + g][2][jj] = sum2(a2[g]);
                }
            }
            __syncthreads();
            if (!hi) {
                const float bi0 = gbi[l * 768 + jj];
                const float bi1 = gbi[l * 768 + 256 + jj];
                const float bi2 = gbi[l * 768 + 512 + jj];
                const float bh0 = gbh[l * 768 + jj];
                const float bh1 = gbh[l * 768 + 256 + jj];
                const float bh2 = gbh[l * 768 + 512 + jj];
                #pragma unroll
                for (int g = 0; g < 2; g++) {
                    int r = r0 + g;
                    float hprev = s_h[l][r][jj];
                    float i0 = sum2(a0[g]) + bi0, h0 = s_p2[r][0][jj] + bh0;
                    float i1 = sum2(a1[g]) + bi1, h1 = s_p2[r][1][jj] + bh1;
                    float i2 = sum2(a2[g]) + bi2, h2 = s_p2[r][2][jj] + bh2;
                    float rr = 1.f / (1.f + __expf(-(i0 + h0)));
                    float z  = 1.f / (1.f + __expf(-(i1 + h1)));
                    float n  = tanhf(i2 + rr * h2);
                    float hn = (1.f - z) * n + z * hprev;
                    s_h[l][r][jj] = hn;
                    s_x[r][jj]    = hn;
                }
            }
            __syncthreads();
        }

        // -------- output projection (per group, K split 4 ways) + log_softmax --------
        {
            int j  = tid2 & 127;
            int sl = tid2 >> 7;                 // 0..3
            u64 acc[2] = {0, 0};
            const uint2* W = (const uint2*)Pout + j;
            #pragma unroll 8
            for (int k4 = sl * 16; k4 < sl * 16 + 16; k4++) {
                uint2 wh = W[k4 * 128];
                u64 wx = cvt2(wh.x), wy = cvt2(wh.y);
                #pragma unroll
                for (int g = 0; g < 2; g++) {
                    ulonglong2 hv = ((const ulonglong2*)s_x[r0 + g])[k4];
                    fma2(acc[g], wx, hv.x);
                    fma2(acc[g], wy, hv.y);
                }
            }
            float* s_op = &s_p2[0][0][0];
            #pragma unroll
            for (int g = 0; g < 2; g++)
                s_op[((r0 + g) * 4 + sl) * 128 + j] = sum2(acc[g]);
            __syncthreads();

            float oacc[G];
            int jo = tid & 127;
            #pragma unroll
            for (int r = 0; r < G; r++) {
                oacc[r] = (tid < 128)
                    ? (out_b[jo] + s_op[(r * 4 + 0) * 128 + jo] + s_op[(r * 4 + 1) * 128 + jo]
                                + s_op[(r * 4 + 2) * 128 + jo] + s_op[(r * 4 + 3) * 128 + jo])
                    : -1e30f;
            }
            float m[G];
            #pragma unroll
            for (int r = 0; r < G; r++) m[r] = oacc[r];
            block_reduce4(m, s_red, tid, true);
            float p[G];
            #pragma unroll
            for (int r = 0; r < G; r++) p[r] = (tid < 128) ? __expf(oacc[r] - m[r]) : 0.f;
            float s[G];
            #pragma unroll
            for (int r = 0; r < G; r++) s[r] = p[r];
            block_reduce4(s, s_red, tid, false);
            if (tid < 128) {
                #pragma unroll
                for (int r = 0; r < G; r++)
                    s_out[r][jo][t & 7] = oacc[r] - m[r] - logf(s[r]);
            }
        }

        // -------- flush staged outputs every 8 steps (1024 coalesced float4) --------
        __syncthreads();
        if ((t & 7) == 7) {
            int g = tid >> 8, rem = tid & 255, j = rem >> 1, half = rem & 1;
            float4 v = *(float4*)&s_out[g][j][half * 4];
            *(float4*)(outp + ((size_t)(b0 + g) * Vv + j) * Tt + (t - 7) + half * 4) = v;
            __syncthreads();
        }
    }
}

// ---------------- launch ----------------
extern "C" void kernel_launch(void* const* d_in, const int* in_sizes, int n_in,
                              void* d_out, int out_size)
{
    const float* x      = (const float*)d_in[0];
    const int*   y      = (const int*)  d_in[1];
    const float* emb    = (const float*)d_in[2];
    const float* attn_w = (const float*)d_in[3];
    const float* attn_b = (const float*)d_in[4];
    const float* comb_w = (const float*)d_in[5];
    const float* comb_b = (const float*)d_in[6];
    const float* gih    = (const float*)d_in[7];
    const float* ghh    = (const float*)d_in[8];
    const float* gbi    = (const float*)d_in[9];
    const float* gbh    = (const float*)d_in[10];
    const float* out_w  = (const float*)d_in[11];
    const float* out_b  = (const float*)d_in[12];

    float* outp  = (float*)d_out;                        // [B,V,T]
    float* attnp = (float*)d_out + (size_t)Bb * Vv * Tt; // [B,T,L]

    pack_all_kernel<<<PACK_BLOCKS + ENC_BLOCKS + TOK_BLOCKS, 256>>>(
        attn_w, comb_w, gih, ghh, out_w, x, emb, attn_b, comb_b);
    decoder_kernel<<<Bb / G, NTH>>>(y, gbi, gbh, out_b, outp, attnp);
}

// round 16
// speedup vs baseline: 1.8649x; 1.8649x over previous
#include <cuda_runtime.h>
#include <cuda_fp16.h>
#include <cuda_bf16.h>
#include <math.h>

#define Bb   512
#define Hh   256
#define Ld   256
#define Tt   64
#define Vv   128
#define NL   2
#define G    4
#define NTH  512

// ---------------- packed bf16 weight scratch (transposed + k-interleaved) ------------
#define OFF_ATTNH 0         // attn h-part: K=256,N=256 -> 65536
#define OFF_COMBA 65536     // comb applied-part:       -> 65536
#define OFF_GIH   131072    // 2 x 256x768 -> 393216
#define OFF_GHH   524288    // 2 x 256x768 -> 393216
#define OFF_OUT   917504    // 256x128 -> 32768
#define PACK_TOTAL 950272

#define PACK_BLOCKS 3712
#define ENC_BLOCKS  32768
#define TOK_BLOCKS  256

__device__ __align__(16) __nv_bfloat16 g_pack[PACK_TOTAL];
__device__ __align__(16) __half g_enc[(size_t)Bb * Hh * Ld];   // fp16 encoder memory
__device__ __align__(16) float  g_Tattn[Vv * Ld];
__device__ __align__(16) float  g_Tcomb[Vv * Hh];

__global__ void pack_all_kernel(const float* __restrict__ aw, const float* __restrict__ cw,
                                const float* __restrict__ gih, const float* __restrict__ ghh,
                                const float* __restrict__ ow, const float* __restrict__ x,
                                const float* __restrict__ emb, const float* __restrict__ ab,
                                const float* __restrict__ cb)
{
    if (blockIdx.x < PACK_BLOCKS) {
        int i = blockIdx.x * blockDim.x + threadIdx.x;
        if (i >= PACK_TOTAL) return;
        float v;
        if (i < 65536) {                        // attn h-part: W[j][256 + k]
            int c = i & 3, j = (i >> 2) & 255, k4 = i >> 10;
            v = aw[j * 512 + 256 + k4 * 4 + c];
        } else if (i < 131072) {                // comb applied-part: W[j][k]
            int r = i - 65536;
            int c = r & 3, j = (r >> 2) & 255, k4 = r >> 10;
            v = cw[j * 512 + k4 * 4 + c];
        } else if (i < 524288) {                // gru ih
            int r = i - 131072;
            int layer = r / 196608; int q = r % 196608;
            int c = q & 3; int t2 = q >> 2; int j = t2 % 768; int k4 = t2 / 768;
            v = gih[layer * 196608 + j * 256 + k4 * 4 + c];
        } else if (i < 917504) {                // gru hh
            int r = i - 524288;
            int layer = r / 196608; int q = r % 196608;
            int c = q & 3; int t2 = q >> 2; int j = t2 % 768; int k4 = t2 / 768;
            v = ghh[layer * 196608 + j * 256 + k4 * 4 + c];
        } else {                                // out
            int r = i - 917504;
            int c = r & 3, j = (r >> 2) & 127, k4 = r >> 9;
            v = ow[j * 256 + k4 * 4 + c];
        }
        g_pack[i] = __float2bfloat16(v);
    } else if (blockIdx.x < PACK_BLOCKS + ENC_BLOCKS) {
        size_t i = (size_t)(blockIdx.x - PACK_BLOCKS) * blockDim.x + threadIdx.x;
        float4 v = ((const float4*)x)[i];
        __half2 h0 = __floats2half2_rn(v.x, v.y);
        __half2 h1 = __floats2half2_rn(v.z, v.w);
        uint2 o;
        o.x = *(unsigned*)&h0;
        o.y = *(unsigned*)&h1;
        ((uint2*)g_enc)[i] = o;
    } else {
        __shared__ float se[Hh];
        int bid = blockIdx.x - PACK_BLOCKS - ENC_BLOCKS;
        int tok = bid & 127;
        bool isComb = bid >= 128;
        int j = threadIdx.x;
        se[j] = emb[tok * Hh + j];
        __syncthreads();
        const float* W = isComb ? (cw + j * 512 + 256) : (aw + j * 512);
        float s = 0.f;
        #pragma unroll 8
        for (int k = 0; k < 256; k++) s += W[k] * se[k];
        if (isComb) g_Tcomb[tok * Hh + j] = s + cb[j];
        else        g_Tattn[tok * Ld + j] = s + ab[j];
    }
}

// ---------------- f32x2 / bf16 helpers ----------------
typedef unsigned long long u64;

__device__ __forceinline__ void fma2(u64& d, u64 a, u64 b) {
    asm("fma.rn.f32x2 %0, %1, %2, %0;" : "+l"(d) : "l"(a), "l"(b));
}
__device__ __forceinline__ float sum2(u64 v) {
    return __uint_as_float((unsigned)v) + __uint_as_float((unsigned)(v >> 32));
}
__device__ __forceinline__ u64 cvt2(unsigned u) {   // bf16x2 -> f32x2, ALU only
    return ((u64)(u & 0xFFFF0000u) << 32) | (u64)(u << 16);
}

// ---------------- vectorized block reduction (4 values, 16 warps) ----------------
__device__ __forceinline__ void block_reduce4(float v[G], float* sm, int tid, bool is_max) {
    __syncthreads();
    #pragma unroll
    for (int g = 0; g < G; g++) {
        #pragma unroll
        for (int o = 16; o > 0; o >>= 1) {
            float oth = __shfl_xor_sync(0xffffffffu, v[g], o);
            v[g] = is_max ? fmaxf(v[g], oth) : (v[g] + oth);
        }
    }
    int wid = tid >> 5;
    if ((tid & 31) == 0) {
        #pragma unroll
        for (int g = 0; g < G; g++) sm[wid * G + g] = v[g];
    }
    __syncthreads();
    #pragma unroll
    for (int g = 0; g < G; g++) {
        float r = sm[g];
        #pragma unroll
        for (int w = 1; w < 16; w++)
            r = is_max ? fmaxf(r, sm[w * G + g]) : (r + sm[w * G + g]);
        v[g] = r;
    }
}

// ---------------- main persistent decoder kernel ----------------
// R13 structure + attn-h matvec pipelined into the out-proj phase of step t-1.
__global__ __launch_bounds__(NTH)
void decoder_kernel(const int*   __restrict__ y,
                    const float* __restrict__ gbi,
                    const float* __restrict__ gbh,
                    const float* __restrict__ out_b,
                    float* __restrict__ outp,
                    float* __restrict__ attnp)
{
    __shared__ __align__(16) float s_h  [NL][G][Hh];
    __shared__ __align__(16) float s_aw [G][Ld];
    __shared__ __align__(16) float s_app[G][Hh];
    __shared__ __align__(16) float s_x  [G][Hh];
    __shared__ __align__(16) float s_p2 [G][3][Hh];
    __shared__ __align__(16) float s_scA[G][Hh];   // pipelined attn h-part (lo K-half)
    __shared__ __align__(16) float s_scB[G][Hh];   // pipelined attn h-part (hi K-half)
    __shared__ __align__(16) float s_out[G][Vv][8];
    __shared__ float s_red[16 * G];
    __shared__ int   s_tok[G];

    const int tid  = threadIdx.x;
    const int wid  = tid >> 5;
    const int lane = tid & 31;
    const int jj   = tid & 255;
    const bool hi  = (tid >= 256);
    const int b0   = blockIdx.x * G;

    const __nv_bfloat16* Pattnh = g_pack + OFF_ATTNH;
    const __nv_bfloat16* Pcomba = g_pack + OFF_COMBA;
    const __nv_bfloat16* Pgih   = g_pack + OFF_GIH;
    const __nv_bfloat16* Pghh   = g_pack + OFF_GHH;
    const __nv_bfloat16* Pout   = g_pack + OFF_OUT;

    for (int i = tid; i < NL * G * Hh; i += NTH)
        (&s_h[0][0][0])[i] = 0.f;
    // zero pipelined attn partials: step 0 has h=0 => partials 0 is exact
    for (int i = tid; i < G * Hh; i += NTH) {
        (&s_scA[0][0])[i] = 0.f;
        (&s_scB[0][0])[i] = 0.f;
    }
    __syncthreads();

    for (int t = 0; t < Tt; t++) {
        // -------- token fetch --------
        if (tid < G)
            s_tok[tid] = (t == 0) ? 0 : y[(b0 + tid) * Tt + t - 1];
        __syncthreads();

        // -------- softmax on pipelined scores (h-part computed last step) --------
        {
            float sc[G];
            #pragma unroll
            for (int g = 0; g < G; g++)
                sc[g] = hi ? -1e30f
                           : (s_scA[g][jj] + s_scB[g][jj] + g_Tattn[s_tok[g] * Ld + jj]);
            float m[G];
            #pragma unroll
            for (int g = 0; g < G; g++) m[g] = sc[g];
            block_reduce4(m, s_red, tid, true);
            float p[G];
            #pragma unroll
            for (int g = 0; g < G; g++) p[g] = hi ? 0.f : __expf(sc[g] - m[g]);
            float s[G];
            #pragma unroll
            for (int g = 0; g < G; g++) s[g] = p[g];
            block_reduce4(s, s_red, tid, false);
            if (!hi) {
                #pragma unroll
                for (int g = 0; g < G; g++) {
                    float a = p[g] * (1.f / s[g]);
                    s_aw[g][jj] = a;
                    attnp[((size_t)(b0 + g) * Tt + t) * Ld + jj] = a;
                }
            }
            __syncthreads();
        }

        // -------- applied = aw @ enc (fp16 enc, warp owns fixed row g) --------
        {
            const int g = wid >> 2;
            const int hbase = (wid & 3) * 64;
            const float4* awp = (const float4*)(s_aw[g]);
            const float4 A0 = awp[lane * 2];
            const float4 A1 = awp[lane * 2 + 1];
            const uint4* xrow =
                (const uint4*)(g_enc + ((size_t)(b0 + g) * Hh + hbase) * Ld) + lane;
            #pragma unroll
            for (int it = 0; it < 64; it += 8) {
                uint4 xv[8];
                #pragma unroll
                for (int u = 0; u < 8; u++) xv[u] = xrow[(it + u) * 32];
                float d[8];
                #pragma unroll
                for (int u = 0; u < 8; u++) {
                    float2 f0 = __half22float2(*(__half2*)&xv[u].x);
                    float2 f1 = __half22float2(*(__half2*)&xv[u].y);
                    float2 f2 = __half22float2(*(__half2*)&xv[u].z);
                    float2 f3 = __half22float2(*(__half2*)&xv[u].w);
                    d[u] = f0.x * A0.x + f0.y * A0.y + f1.x * A0.z + f1.y * A0.w
                         + f2.x * A1.x + f2.y * A1.y + f3.x * A1.z + f3.y * A1.w;
                }
                #pragma unroll
                for (int u = 0; u < 8; u++) {
                    #pragma unroll
                    for (int o = 16; o > 0; o >>= 1)
                        d[u] += __shfl_xor_sync(0xffffffffu, d[u], o);
                }
                if (lane == 0) {
                    #pragma unroll
                    for (int u = 0; u < 8; u++) s_app[g][hbase + it + u] = d[u];
                }
            }
        }
        __syncthreads();

        // -------- combine: applied-part lo/hi K-halves; e-part from table --------
        {
            u64 acc[G] = {0, 0, 0, 0};
            const uint2* W = (const uint2*)Pcomba + (hi ? 32 * 256 : 0) + jj;
            const int kbase = hi ? 32 : 0;
            #pragma unroll 8
            for (int k4 = 0; k4 < 32; k4++) {
                uint2 wh = W[k4 * 256];
                u64 wx = cvt2(wh.x), wy = cvt2(wh.y);
                #pragma unroll
                for (int g = 0; g < G; g++) {
                    ulonglong2 xv = ((const ulonglong2*)(&s_app[g][0]))[kbase + k4];
                    fma2(acc[g], wx, xv.x);
                    fma2(acc[g], wy, xv.y);
                }
            }
            if (hi) {
                #pragma unroll
                for (int g = 0; g < G; g++) s_p2[g][0][jj] = sum2(acc[g]);
            }
            __syncthreads();
            if (!hi) {
                #pragma unroll
                for (int g = 0; g < G; g++)
                    s_x[g][jj] = fmaxf(sum2(acc[g]) + s_p2[g][0][jj]
                                       + g_Tcomb[s_tok[g] * Hh + jj], 0.f);
            }
            __syncthreads();
        }

        // -------- GRU layers: lo half = ih matvec, hi half = hh matvec --------
        #pragma unroll
        for (int l = 0; l < NL; l++) {
            u64 a0[G] = {0,0,0,0}, a1[G] = {0,0,0,0}, a2[G] = {0,0,0,0};
            const uint2* W =
                (const uint2*)((hi ? Pghh : Pgih) + l * 196608) + jj;
            const float* vb = hi ? &s_h[l][0][0] : &s_x[0][0];
            #pragma unroll 4
            for (int k4 = 0; k4 < 64; k4++) {
                uint2 wh0 = W[k4 * 768];
                uint2 wh1 = W[k4 * 768 + 256];
                uint2 wh2 = W[k4 * 768 + 512];
                u64 w0x = cvt2(wh0.x), w0y = cvt2(wh0.y);
                u64 w1x = cvt2(wh1.x), w1y = cvt2(wh1.y);
                u64 w2x = cvt2(wh2.x), w2y = cvt2(wh2.y);
                #pragma unroll
                for (int g = 0; g < G; g++) {
                    ulonglong2 xv = ((const ulonglong2*)(vb + g * Hh))[k4];
                    fma2(a0[g], w0x, xv.x); fma2(a0[g], w0y, xv.y);
                    fma2(a1[g], w1x, xv.x); fma2(a1[g], w1y, xv.y);
                    fma2(a2[g], w2x, xv.x); fma2(a2[g], w2y, xv.y);
                }
            }
            if (hi) {
                #pragma unroll
                for (int g = 0; g < G; g++) {
                    s_p2[g][0][jj] = sum2(a0[g]);
                    s_p2[g][1][jj] = sum2(a1[g]);
                    s_p2[g][2][jj] = sum2(a2[g]);
                }
            }
            __syncthreads();
            if (!hi) {
                const float bi0 = gbi[l * 768 + jj];
                const float bi1 = gbi[l * 768 + 256 + jj];
                const float bi2 = gbi[l * 768 + 512 + jj];
                const float bh0 = gbh[l * 768 + jj];
                const float bh1 = gbh[l * 768 + 256 + jj];
                const float bh2 = gbh[l * 768 + 512 + jj];
                #pragma unroll
                for (int g = 0; g < G; g++) {
                    float hprev = s_h[l][g][jj];
                    float i0 = sum2(a0[g]) + bi0, h0 = s_p2[g][0][jj] + bh0;
                    float i1 = sum2(a1[g]) + bi1, h1 = s_p2[g][1][jj] + bh1;
                    float i2 = sum2(a2[g]) + bi2, h2 = s_p2[g][2][jj] + bh2;
                    float r = 1.f / (1.f + __expf(-(i0 + h0)));
                    float z = 1.f / (1.f + __expf(-(i1 + h1)));
                    float n = tanhf(i2 + r * h2);
                    float hn = (1.f - z) * n + z * hprev;
                    s_h[l][g][jj] = hn;
                    s_x[g][jj]    = hn;
                }
            }
            __syncthreads();
        }

        // -------- out-proj + pipelined attn-h(t+1), one barrier-free region --------
        {
            int j  = tid & 127;
            int sl = tid >> 7;
            u64 acc[G] = {0, 0, 0, 0};
            const uint2* W = (const uint2*)Pout + j;
            #pragma unroll 8
            for (int k4 = sl * 16; k4 < sl * 16 + 16; k4++) {
                uint2 wh = W[k4 * 128];
                u64 wx = cvt2(wh.x), wy = cvt2(wh.y);
                #pragma unroll
                for (int g = 0; g < G; g++) {
                    ulonglong2 hv = ((const ulonglong2*)s_x[g])[k4];
                    fma2(acc[g], wx, hv.x);
                    fma2(acc[g], wy, hv.y);
                }
            }
            float* s_op = &s_p2[0][0][0];
            #pragma unroll
            for (int g = 0; g < G; g++) s_op[(g * 4 + sl) * 128 + j] = sum2(acc[g]);

            // attn h-part for step t+1 (reads s_h[0], final since GRU barrier)
            if (t < Tt - 1) {
                u64 aacc[G] = {0, 0, 0, 0};
                const uint2* Wa = (const uint2*)Pattnh + (hi ? 32 * 256 : 0) + jj;
                const int kbase = hi ? 32 : 0;
                #pragma unroll 8
                for (int k4 = 0; k4 < 32; k4++) {
                    uint2 wh = Wa[k4 * 256];
                    u64 wx = cvt2(wh.x), wy = cvt2(wh.y);
                    #pragma unroll
                    for (int g = 0; g < G; g++) {
                        ulonglong2 xv = ((const ulonglong2*)(&s_h[0][g][0]))[kbase + k4];
                        fma2(aacc[g], wx, xv.x);
                        fma2(aacc[g], wy, xv.y);
                    }
                }
                float* dstA = hi ? &s_scB[0][0] : &s_scA[0][0];
                #pragma unroll
                for (int g = 0; g < G; g++) dstA[g * Hh + jj] = sum2(aacc[g]);
            }
            __syncthreads();

            float oacc[G];
            #pragma unroll
            for (int g = 0; g < G; g++) {
                oacc[g] = (tid < 128)
                    ? (out_b[j] + s_op[(g * 4 + 0) * 128 + j] + s_op[(g * 4 + 1) * 128 + j]
                               + s_op[(g * 4 + 2) * 128 + j] + s_op[(g * 4 + 3) * 128 + j])
                    : -1e30f;
            }
            float m[G];
            #pragma unroll
            for (int g = 0; g < G; g++) m[g] = oacc[g];
            block_reduce4(m, s_red, tid, true);
            float p[G];
            #pragma unroll
            for (int g = 0; g < G; g++) p[g] = (tid < 128) ? __expf(oacc[g] - m[g]) : 0.f;
            float s[G];
            #pragma unroll
            for (int g = 0; g < G; g++) s[g] = p[g];
            block_reduce4(s, s_red, tid, false);
            if (tid < 128) {
                #pragma unroll
                for (int g = 0; g < G; g++)
                    s_out[g][j][t & 7] = oacc[g] - m[g] - logf(s[g]);
            }
        }

        // -------- flush staged outputs every 8 steps --------
        __syncthreads();
        if ((t & 7) == 7) {
            int g = tid >> 7, j = tid & 127;
            float4 v0 = *(float4*)&s_out[g][j][0];
            float4 v1 = *(float4*)&s_out[g][j][4];
            float4* dst = (float4*)(outp + ((size_t)(b0 + g) * Vv + j) * Tt + (t - 7));
            dst[0] = v0;
            dst[1] = v1;
            __syncthreads();
        }
    }
}

// ---------------- launch ----------------
extern "C" void kernel_launch(void* const* d_in, const int* in_sizes, int n_in,
                              void* d_out, int out_size)
{
    const float* x      = (const float*)d_in[0];
    const int*   y      = (const int*)  d_in[1];
    const float* emb    = (const float*)d_in[2];
    const float* attn_w = (const float*)d_in[3];
    const float* attn_b = (const float*)d_in[4];
    const float* comb_w = (const float*)d_in[5];
    const float* comb_b = (const float*)d_in[6];
    const float* gih    = (const float*)d_in[7];
    const float* ghh    = (const float*)d_in[8];
    const float* gbi    = (const float*)d_in[9];
    const float* gbh    = (const float*)d_in[10];
    const float* out_w  = (const float*)d_in[11];
    const float* out_b  = (const float*)d_in[12];

    float* outp  = (float*)d_out;                        // [B,V,T]
    float* attnp = (float*)d_out + (size_t)Bb * Vv * Tt; // [B,T,L]

    pack_all_kernel<<<PACK_BLOCKS + ENC_BLOCKS + TOK_BLOCKS, 256>>>(
        attn_w, comb_w, gih, ghh, out_w, x, emb, attn_b, comb_b);
    decoder_kernel<<<Bb / G, NTH>>>(y, gbi, gbh, out_b, outp, attnp);
}

// round 17
// speedup vs baseline: 3.1676x; 1.6985x over previous
#include <cuda_runtime.h>
#include <cuda_fp16.h>
#include <cuda_bf16.h>
#include <math.h>

#define Bb   512
#define Hh   256
#define Ld   256
#define Tt   64
#define Vv   128
#define NL   2
#define G    4
#define NTH  512

// ---------------- fragment-packed bf16 weights ----------------
// Tile (nt,kt) of W[N][256]: 512B = 32 lanes x uint4. Lane's uint4 = {a0,a1,a2,a3}
// of mma.m16n8k16 row-major A: a0=(r,kl) a1=(r+8,kl) a2=(r,kh) a3=(r+8,kh),
// r = nt*16 + lane/4, k pair = kt*16 + (lane%4)*2 (+8 for kh).
#define OFF_ATTNH 0         // 16nt x 16kt -> 65536 halves
#define OFF_COMBA 65536
#define OFF_GIH   131072    // 2 layers x 48nt x 16kt = 196608 each
#define OFF_GHH   524288
#define OFF_OUT   917504    // 8nt
#define PACK_TOTAL 950272

#define PACK_BLOCKS 3712
#define ENC_BLOCKS  32768
#define TOK_BLOCKS  256

__device__ __align__(16) __nv_bfloat16 g_pack[PACK_TOTAL];
__device__ __align__(16) __half g_enc[(size_t)Bb * Hh * Ld];
__device__ __align__(16) float  g_Tattn[Vv * Ld];
__device__ __align__(16) float  g_Tcomb[Vv * Hh];

__global__ void pack_all_kernel(const float* __restrict__ aw, const float* __restrict__ cw,
                                const float* __restrict__ gih, const float* __restrict__ ghh,
                                const float* __restrict__ ow, const float* __restrict__ x,
                                const float* __restrict__ emb, const float* __restrict__ ab,
                                const float* __restrict__ cb)
{
    if (blockIdx.x < PACK_BLOCKS) {
        int i = blockIdx.x * blockDim.x + threadIdx.x;
        if (i >= PACK_TOTAL) return;
        // region select
        int li; int kind; int layer = 0;
        if (i < 65536)        { kind = 0; li = i; }
        else if (i < 131072)  { kind = 1; li = i - 65536; }
        else if (i < 524288)  { kind = 2; li = (i - 131072) % 196608; layer = (i - 131072) / 196608; }
        else if (i < 917504)  { kind = 3; li = (i - 524288) % 196608; layer = (i - 524288) / 196608; }
        else                  { kind = 4; li = i - 917504; }
        // fragment decode
        int tile_lin = li >> 8;
        int r    = li & 255;
        int lane = r >> 3;
        int h    = r & 7;
        int reg  = h >> 1;
        int pos  = h & 1;
        int nt = tile_lin >> 4, kt = tile_lin & 15;
        int g_ = lane >> 2, tig = lane & 3;
        int row = nt * 16 + g_ + (reg & 1) * 8;
        int col = kt * 16 + tig * 2 + pos + (reg >> 1) * 8;
        float v;
        switch (kind) {
            case 0:  v = aw[row * 512 + 256 + col]; break;
            case 1:  v = cw[row * 512 + col];       break;
            case 2:  v = gih[layer * 196608 + row * 256 + col]; break;
            case 3:  v = ghh[layer * 196608 + row * 256 + col]; break;
            default: v = ow[row * 256 + col];       break;
        }
        g_pack[i] = __float2bfloat16(v);
    } else if (blockIdx.x < PACK_BLOCKS + ENC_BLOCKS) {
        size_t i = (size_t)(blockIdx.x - PACK_BLOCKS) * blockDim.x + threadIdx.x;
        float4 v = ((const float4*)x)[i];
        __half2 h0 = __floats2half2_rn(v.x, v.y);
        __half2 h1 = __floats2half2_rn(v.z, v.w);
        uint2 o;
        o.x = *(unsigned*)&h0;
        o.y = *(unsigned*)&h1;
        ((uint2*)g_enc)[i] = o;
    } else {
        __shared__ float se[Hh];
        int bid = blockIdx.x - PACK_BLOCKS - ENC_BLOCKS;
        int tok = bid & 127;
        bool isComb = bid >= 128;
        int j = threadIdx.x;
        se[j] = emb[tok * Hh + j];
        __syncthreads();
        const float* W = isComb ? (cw + j * 512 + 256) : (aw + j * 512);
        float s = 0.f;
        #pragma unroll 8
        for (int k = 0; k < 256; k++) s += W[k] * se[k];
        if (isComb) g_Tcomb[tok * Hh + j] = s + cb[j];
        else        g_Tattn[tok * Ld + j] = s + ab[j];
    }
}

// ---------------- mma helper ----------------
__device__ __forceinline__ void mma16816(float& d0, float& d1, float& d2, float& d3,
                                         unsigned a0, unsigned a1, unsigned a2, unsigned a3,
                                         unsigned b0, unsigned b1)
{
    asm volatile("mma.sync.aligned.m16n8k16.row.col.f32.bf16.bf16.f32 "
        "{%0,%1,%2,%3}, {%4,%5,%6,%7}, {%8,%9}, {%0,%1,%2,%3};"
        : "+f"(d0), "+f"(d1), "+f"(d2), "+f"(d3)
        : "r"(a0), "r"(a1), "r"(a2), "r"(a3), "r"(b0), "r"(b1));
}

// ---------------- block reduce (4 values, 16 warps) ----------------
__device__ __forceinline__ void block_reduce4(float v[G], float* sm, int tid, bool is_max) {
    __syncthreads();
    #pragma unroll
    for (int g = 0; g < G; g++) {
        #pragma unroll
        for (int o = 16; o > 0; o >>= 1) {
            float oth = __shfl_xor_sync(0xffffffffu, v[g], o);
            v[g] = is_max ? fmaxf(v[g], oth) : (v[g] + oth);
        }
    }
    int wid = tid >> 5;
    if ((tid & 31) == 0) {
        #pragma unroll
        for (int g = 0; g < G; g++) sm[wid * G + g] = v[g];
    }
    __syncthreads();
    #pragma unroll
    for (int g = 0; g < G; g++) {
        float r = sm[g];
        #pragma unroll
        for (int w = 1; w < 16; w++)
            r = is_max ? fmaxf(r, sm[w * G + g]) : (r + sm[w * G + g]);
        v[g] = r;
    }
}

// ---------------- dynamic smem (byte offsets) ----------------
#define SB_H    0        // fp32 h       [2][4][256]  8192
#define SB_AW   8192     // fp32 aw      [4][256]     4096
#define SB_APP  12288    // fp32 applied [4][256]     4096
#define SB_SC   16384    // fp32 scores  [256][4]     4096
#define SB_GI   20480    // fp32 ih dots [768][4]     12288
#define SB_GH   32768    // fp32 hh dots [768][4]     12288
#define SB_OP   45056    // fp32 out dots[128][4]     2048
#define SB_OUT  47104    // fp32 staging [4][128][8]  16384
#define SB_RED  63488    // 256
#define SB_TOK  63744    // 16
#define SB_HB   63760    // bf16 h copy [2][4][264]   4224
#define SB_XB   67984    // bf16 x      [4][264]      2112
#define SB_AB   70096    // bf16 applied[4][264]      2112
#define SMEM_BYTES 72208
#define BSTRIDE 264

// ---------------- main persistent decoder kernel ----------------
__global__ __launch_bounds__(NTH)
void decoder_kernel(const int*   __restrict__ y,
                    const float* __restrict__ gbi,
                    const float* __restrict__ gbh,
                    const float* __restrict__ out_b,
                    float* __restrict__ outp,
                    float* __restrict__ attnp)
{
    extern __shared__ __align__(16) char dsm[];
    float* s_h   = (float*)(dsm + SB_H);
    float* s_aw  = (float*)(dsm + SB_AW);
    float* s_app = (float*)(dsm + SB_APP);
    float* s_sc  = (float*)(dsm + SB_SC);
    float* s_gi  = (float*)(dsm + SB_GI);
    float* s_gh  = (float*)(dsm + SB_GH);
    float* s_op  = (float*)(dsm + SB_OP);
    float* s_out = (float*)(dsm + SB_OUT);
    float* s_red = (float*)(dsm + SB_RED);
    int*   s_tok = (int*)(dsm + SB_TOK);
    __nv_bfloat16* s_hb = (__nv_bfloat16*)(dsm + SB_HB);
    __nv_bfloat16* s_xb = (__nv_bfloat16*)(dsm + SB_XB);
    __nv_bfloat16* s_ab = (__nv_bfloat16*)(dsm + SB_AB);

    const int tid  = threadIdx.x;
    const int wid  = tid >> 5;
    const int lane = tid & 31;
    const int g_   = lane >> 2;           // mma group id
    const int tig  = lane & 3;            // thread in group
    const int jj   = tid & 255;
    const bool hi  = (tid >= 256);
    const int b0   = blockIdx.x * G;
    const int bofs = (g_ & 3) * BSTRIDE + tig * 2;   // B-fragment base (halves)

    for (int i = tid; i < 2048; i += NTH) s_h[i] = 0.f;
    for (int i = tid; i < 2 * G * BSTRIDE; i += NTH) s_hb[i] = __float2bfloat16(0.f);
    __syncthreads();

    for (int t = 0; t < Tt; t++) {
        // -------- token fetch + attention-score mma (B = h0 bf16) --------
        if (tid < G)
            s_tok[tid] = (t == 0) ? 0 : y[(b0 + tid) * Tt + t - 1];
        {
            float d0 = 0.f, d1 = 0.f, d2 = 0.f, d3 = 0.f;
            const uint4* A = (const uint4*)(g_pack + OFF_ATTNH) + wid * 512 + lane;
            const __nv_bfloat16* B = s_hb + bofs;   // layer 0 h
            #pragma unroll
            for (int kt = 0; kt < 16; kt++) {
                uint4 a = A[kt * 32];
                unsigned bb0 = *(const unsigned*)(B + kt * 16);
                unsigned bb1 = *(const unsigned*)(B + kt * 16 + 8);
                mma16816(d0, d1, d2, d3, a.x, a.y, a.z, a.w, bb0, bb1);
            }
            if (tig < 2) {
                int row = wid * 16 + g_;
                *(float2*)&s_sc[row * 4 + tig * 2]       = make_float2(d0, d1);
                *(float2*)&s_sc[(row + 8) * 4 + tig * 2] = make_float2(d2, d3);
            }
        }
        __syncthreads();

        // -------- softmax (scores[n][g] + token table) --------
        {
            float sc[G];
            if (!hi) {
                float4 s4 = ((const float4*)s_sc)[jj];
                const float* s4f = (const float*)&s4;
                #pragma unroll
                for (int g = 0; g < G; g++)
                    sc[g] = s4f[g] + g_Tattn[s_tok[g] * Ld + jj];
            } else {
                #pragma unroll
                for (int g = 0; g < G; g++) sc[g] = -1e30f;
            }
            float m[G];
            #pragma unroll
            for (int g = 0; g < G; g++) m[g] = sc[g];
            block_reduce4(m, s_red, tid, true);
            float p[G];
            #pragma unroll
            for (int g = 0; g < G; g++) p[g] = hi ? 0.f : __expf(sc[g] - m[g]);
            float s[G];
            #pragma unroll
            for (int g = 0; g < G; g++) s[g] = p[g];
            block_reduce4(s, s_red, tid, false);
            if (!hi) {
                #pragma unroll
                for (int g = 0; g < G; g++) {
                    float a = p[g] * (1.f / s[g]);
                    s_aw[g * Ld + jj] = a;
                    attnp[((size_t)(b0 + g) * Tt + t) * Ld + jj] = a;
                }
            }
            __syncthreads();
        }

        // -------- applied = aw @ enc (fp16 enc, warp owns fixed row) --------
        {
            const int g = wid >> 2;
            const int hbase = (wid & 3) * 64;
            const float4* awp = (const float4*)(s_aw + g * Ld);
            const float4 A0 = awp[lane * 2];
            const float4 A1 = awp[lane * 2 + 1];
            const uint4* xrow =
                (const uint4*)(g_enc + ((size_t)(b0 + g) * Hh + hbase) * Ld) + lane;
            #pragma unroll
            for (int it = 0; it < 64; it += 8) {
                uint4 xv[8];
                #pragma unroll
                for (int u = 0; u < 8; u++) xv[u] = xrow[(it + u) * 32];
                float d[8];
                #pragma unroll
                for (int u = 0; u < 8; u++) {
                    float2 f0 = __half22float2(*(__half2*)&xv[u].x);
                    float2 f1 = __half22float2(*(__half2*)&xv[u].y);
                    float2 f2 = __half22float2(*(__half2*)&xv[u].z);
                    float2 f3 = __half22float2(*(__half2*)&xv[u].w);
                    d[u] = f0.x * A0.x + f0.y * A0.y + f1.x * A0.z + f1.y * A0.w
                         + f2.x * A1.x + f2.y * A1.y + f3.x * A1.z + f3.y * A1.w;
                }
                #pragma unroll
                for (int u = 0; u < 8; u++) {
                    #pragma unroll
                    for (int o = 16; o > 0; o >>= 1)
                        d[u] += __shfl_xor_sync(0xffffffffu, d[u], o);
                }
                if (lane == 0) {
                    #pragma unroll
                    for (int u = 0; u < 8; u++) s_app[g * Hh + hbase + it + u] = d[u];
                }
            }
        }
        __syncthreads();

        // -------- convert applied -> bf16 --------
        {
            int n = tid >> 7;
            int k = (tid * 2) & 255;
            float2 v = *(const float2*)&s_app[n * 256 + k];
            __nv_bfloat162 bv = __floats2bfloat162_rn(v.x, v.y);
            *(unsigned*)(s_ab + n * BSTRIDE + k) = *(unsigned*)&bv;
        }
        __syncthreads();

        // -------- combine mma: D + Tcomb, relu -> x bf16 --------
        {
            float d0 = 0.f, d1 = 0.f, d2 = 0.f, d3 = 0.f;
            const uint4* A = (const uint4*)(g_pack + OFF_COMBA) + wid * 512 + lane;
            const __nv_bfloat16* B = s_ab + bofs;
            #pragma unroll
            for (int kt = 0; kt < 16; kt++) {
                uint4 a = A[kt * 32];
                unsigned bb0 = *(const unsigned*)(B + kt * 16);
                unsigned bb1 = *(const unsigned*)(B + kt * 16 + 8);
                mma16816(d0, d1, d2, d3, a.x, a.y, a.z, a.w, bb0, bb1);
            }
            if (tig < 2) {
                int n1 = wid * 16 + g_, n2 = n1 + 8;
                int bA = tig * 2, bB = tig * 2 + 1;
                float v;
                v = fmaxf(d0 + g_Tcomb[s_tok[bA] * Hh + n1], 0.f);
                s_xb[bA * BSTRIDE + n1] = __float2bfloat16(v);
                v = fmaxf(d1 + g_Tcomb[s_tok[bB] * Hh + n1], 0.f);
                s_xb[bB * BSTRIDE + n1] = __float2bfloat16(v);
                v = fmaxf(d2 + g_Tcomb[s_tok[bA] * Hh + n2], 0.f);
                s_xb[bA * BSTRIDE + n2] = __float2bfloat16(v);
                v = fmaxf(d3 + g_Tcomb[s_tok[bB] * Hh + n2], 0.f);
                s_xb[bB * BSTRIDE + n2] = __float2bfloat16(v);
            }
        }
        __syncthreads();

        // -------- GRU layers --------
        #pragma unroll
        for (int l = 0; l < NL; l++) {
            // mma: 96 tiles (48 ih + 48 hh), warp wid owns tiles wid*6..+5
            {
                float d[6][4];
                #pragma unroll
                for (int i = 0; i < 6; i++) {
                    d[i][0] = 0.f; d[i][1] = 0.f; d[i][2] = 0.f; d[i][3] = 0.f;
                }
                const uint4* Aih = (const uint4*)(g_pack + OFF_GIH) + l * 24576 + lane;
                const uint4* Ahh = (const uint4*)(g_pack + OFF_GHH) + l * 24576 + lane;
                const __nv_bfloat16* Bx = s_xb + bofs;
                const __nv_bfloat16* Bh = s_hb + l * G * BSTRIDE + bofs;
                #pragma unroll
                for (int i = 0; i < 6; i++) {
                    int T = wid * 6 + i;
                    bool isHH = T >= 48;
                    int nt = isHH ? T - 48 : T;
                    const uint4* A = (isHH ? Ahh : Aih) + nt * 512;
                    const __nv_bfloat16* B = isHH ? Bh : Bx;
                    #pragma unroll
                    for (int kt = 0; kt < 16; kt++) {
                        uint4 a = A[kt * 32];
                        unsigned bb0 = *(const unsigned*)(B + kt * 16);
                        unsigned bb1 = *(const unsigned*)(B + kt * 16 + 8);
                        mma16816(d[i][0], d[i][1], d[i][2], d[i][3],
                                 a.x, a.y, a.z, a.w, bb0, bb1);
                    }
                }
                if (tig < 2) {
                    #pragma unroll
                    for (int i = 0; i < 6; i++) {
                        int T = wid * 6 + i;
                        bool isHH = T >= 48;
                        int nt = isHH ? T - 48 : T;
                        float* arr = isHH ? s_gh : s_gi;
                        int row = nt * 16 + g_;
                        *(float2*)&arr[row * 4 + tig * 2]       = make_float2(d[i][0], d[i][1]);
                        *(float2*)&arr[(row + 8) * 4 + tig * 2] = make_float2(d[i][2], d[i][3]);
                    }
                }
            }
            __syncthreads();

            // gates (lo half), write h fp32 + bf16 copies
            if (!hi) {
                float4 i0v = ((const float4*)s_gi)[jj];
                float4 i1v = ((const float4*)s_gi)[jj + 256];
                float4 i2v = ((const float4*)s_gi)[jj + 512];
                float4 h0v = ((const float4*)s_gh)[jj];
                float4 h1v = ((const float4*)s_gh)[jj + 256];
                float4 h2v = ((const float4*)s_gh)[jj + 512];
                const float bi0 = gbi[l * 768 + jj];
                const float bi1 = gbi[l * 768 + 256 + jj];
                const float bi2 = gbi[l * 768 + 512 + jj];
                const float bh0 = gbh[l * 768 + jj];
                const float bh1 = gbh[l * 768 + 256 + jj];
                const float bh2 = gbh[l * 768 + 512 + jj];
                const float* f0 = (const float*)&i0v;
                const float* f1 = (const float*)&i1v;
                const float* f2 = (const float*)&i2v;
                const float* q0 = (const float*)&h0v;
                const float* q1 = (const float*)&h1v;
                const float* q2 = (const float*)&h2v;
                #pragma unroll
                for (int g = 0; g < G; g++) {
                    float hprev = s_h[(l * G + g) * Hh + jj];
                    float i0 = f0[g] + bi0, h0 = q0[g] + bh0;
                    float i1 = f1[g] + bi1, h1 = q1[g] + bh1;
                    float i2 = f2[g] + bi2, h2 = q2[g] + bh2;
                    float r = 1.f / (1.f + __expf(-(i0 + h0)));
                    float z = 1.f / (1.f + __expf(-(i1 + h1)));
                    float n = tanhf(i2 + r * h2);
                    float hn = (1.f - z) * n + z * hprev;
                    s_h[(l * G + g) * Hh + jj] = hn;
                    __nv_bfloat16 hb = __float2bfloat16(hn);
                    s_hb[(l * G + g) * BSTRIDE + jj] = hb;
                    s_xb[g * BSTRIDE + jj] = hb;
                }
            }
            __syncthreads();
        }

        // -------- output projection mma (warps 0-7) --------
        if (wid < 8) {
            float d0 = 0.f, d1 = 0.f, d2 = 0.f, d3 = 0.f;
            const uint4* A = (const uint4*)(g_pack + OFF_OUT) + wid * 512 + lane;
            const __nv_bfloat16* B = s_xb + bofs;
            #pragma unroll
            for (int kt = 0; kt < 16; kt++) {
                uint4 a = A[kt * 32];
                unsigned bb0 = *(const unsigned*)(B + kt * 16);
                unsigned bb1 = *(const unsigned*)(B + kt * 16 + 8);
                mma16816(d0, d1, d2, d3, a.x, a.y, a.z, a.w, bb0, bb1);
            }
            if (tig < 2) {
                int row = wid * 16 + g_;
                *(float2*)&s_op[row * 4 + tig * 2]       = make_float2(d0, d1);
                *(float2*)&s_op[(row + 8) * 4 + tig * 2] = make_float2(d2, d3);
            }
        }
        __syncthreads();

        // -------- log_softmax --------
        {
            int j = tid & 127;
            float oacc[G];
            if (tid < 128) {
                float4 o4 = ((const float4*)s_op)[j];
                const float* of = (const float*)&o4;
                #pragma unroll
                for (int g = 0; g < G; g++) oacc[g] = out_b[j] + of[g];
            } else {
                #pragma unroll
                for (int g = 0; g < G; g++) oacc[g] = -1e30f;
            }
            float m[G];
            #pragma unroll
            for (int g = 0; g < G; g++) m[g] = oacc[g];
            block_reduce4(m, s_red, tid, true);
            float p[G];
            #pragma unroll
            for (int g = 0; g < G; g++) p[g] = (tid < 128) ? __expf(oacc[g] - m[g]) : 0.f;
            float s[G];
            #pragma unroll
            for (int g = 0; g < G; g++) s[g] = p[g];
            block_reduce4(s, s_red, tid, false);
            if (tid < 128) {
                #pragma unroll
                for (int g = 0; g < G; g++)
                    s_out[(g * Vv + j) * 8 + (t & 7)] = oacc[g] - m[g] - logf(s[g]);
            }
        }

        // -------- flush staged outputs every 8 steps --------
        __syncthreads();
        if ((t & 7) == 7) {
            int g = tid >> 7, j = tid & 127;
            float4 v0 = *(float4*)&s_out[(g * Vv + j) * 8 + 0];
            float4 v1 = *(float4*)&s_out[(g * Vv + j) * 8 + 4];
            float4* dst = (float4*)(outp + ((size_t)(b0 + g) * Vv + j) * Tt + (t - 7));
            dst[0] = v0;
            dst[1] = v1;
            __syncthreads();
        }
    }
}

// ---------------- launch ----------------
extern "C" void kernel_launch(void* const* d_in, const int* in_sizes, int n_in,
                              void* d_out, int out_size)
{
    const float* x      = (const float*)d_in[0];
    const int*   y      = (const int*)  d_in[1];
    const float* emb    = (const float*)d_in[2];
    const float* attn_w = (const float*)d_in[3];
    const float* attn_b = (const float*)d_in[4];
    const float* comb_w = (const float*)d_in[5];
    const float* comb_b = (const float*)d_in[6];
    const float* gih    = (const float*)d_in[7];
    const float* ghh    = (const float*)d_in[8];
    const float* gbi    = (const float*)d_in[9];
    const float* gbh    = (const float*)d_in[10];
    const float* out_w  = (const float*)d_in[11];
    const float* out_b  = (const float*)d_in[12];

    float* outp  = (float*)d_out;                        // [B,V,T]
    float* attnp = (float*)d_out + (size_t)Bb * Vv * Tt; // [B,T,L]

    cudaFuncSetAttribute(decoder_kernel,
                         cudaFuncAttributeMaxDynamicSharedMemorySize, SMEM_BYTES);

    pack_all_kernel<<<PACK_BLOCKS + ENC_BLOCKS + TOK_BLOCKS, 256>>>(
        attn_w, comb_w, gih, ghh, out_w, x, emb, attn_b, comb_b);
    decoder_kernel<<<Bb / G, NTH, SMEM_BYTES>>>(y, gbi, gbh, out_b, outp, attnp);
}